// round 7
// baseline (speedup 1.0000x reference)
#include <cuda_runtime.h>

// q,k,v: (8,256,96,96) f32; kernel_h/w: (256,13) f32; out f32 same shape.
// Per (b,c): 4 GEMMs 96^3 + 2 row-softmaxes + banded Toeplitz add.
// 512 threads/CTA, 3x6 register tile, f32x2 packed FMA, 4 smem buffers.

#define HW    96
#define PCH   100            // pitch: mult of 4 (float4 loads), even (8B LDS.64)
#define BUFN  (HW * PCH)     // 9600 floats
#define KS    13
#define NT    512

typedef unsigned long long u64;

__device__ __forceinline__ u64 splat2(float x) {
    u64 r; unsigned u = __float_as_uint(x);
    asm("mov.b64 %0, {%1, %2};" : "=l"(r) : "r"(u), "r"(u));
    return r;
}
__device__ __forceinline__ void unpack2(u64 v, float& x, float& y) {
    unsigned a, b;
    asm("mov.b64 {%0, %1}, %2;" : "=r"(a), "=r"(b) : "l"(v));
    x = __uint_as_float(a); y = __uint_as_float(b);
}
__device__ __forceinline__ void ffma2(u64& c, u64 a, u64 b) {
    asm("fma.rn.f32x2 %0, %1, %2, %0;" : "+l"(c) : "l"(a), "l"(b));
}

// acc[i][jp] (i over 3 m-rows, jp over 3 n-pairs):
//   C[ty3+i][tx6+2jp .. +1] = sum_k A_elem(m,k) * B[k*PCH + n]
// A_elem(m,k) = A[m*AM + k*AK]  (AM=PCH,AK=1: natural [m][k]; AM=1,AK=PCH: k-major [k][m])
template<int AM, int AK>
__device__ __forceinline__ void gemm96(const float* __restrict__ A,
                                       const float* __restrict__ B,
                                       int ty3, int tx6, u64 acc[3][3]) {
#pragma unroll
    for (int i = 0; i < 3; ++i)
#pragma unroll
        for (int j = 0; j < 3; ++j) acc[i][j] = 0ull;

    const float* ap = A + ty3 * AM;
    const float* bp = B + tx6;
#pragma unroll 4
    for (int kk = 0; kk < HW; ++kk) {
        u64 bv0 = *reinterpret_cast<const u64*>(bp);
        u64 bv1 = *reinterpret_cast<const u64*>(bp + 2);
        u64 bv2 = *reinterpret_cast<const u64*>(bp + 4);
        u64 a0 = splat2(ap[0]);
        u64 a1 = splat2(ap[AM]);
        u64 a2 = splat2(ap[2 * AM]);
        ffma2(acc[0][0], a0, bv0); ffma2(acc[0][1], a0, bv1); ffma2(acc[0][2], a0, bv2);
        ffma2(acc[1][0], a1, bv0); ffma2(acc[1][1], a1, bv1); ffma2(acc[1][2], a1, bv2);
        ffma2(acc[2][0], a2, bv0); ffma2(acc[2][1], a2, bv1); ffma2(acc[2][2], a2, bv2);
        ap += AK; bp += PCH;
    }
}

// Row softmax (rows = m across the 16 tx lanes) + band, store natural dst[m][n]
// (TRANS=0) or transposed dstT[n][m] (TRANS=1).
template<int TRANS>
__device__ __forceinline__ void softmax_band_store(u64 acc[3][3], float* __restrict__ dst,
                                                   const float* __restrict__ kern,
                                                   int ty3, int tx6) {
#pragma unroll
    for (int i = 0; i < 3; ++i) {
        float s[6];
        unpack2(acc[i][0], s[0], s[1]);
        unpack2(acc[i][1], s[2], s[3]);
        unpack2(acc[i][2], s[4], s[5]);

        float m = s[0];
#pragma unroll
        for (int jj = 1; jj < 6; ++jj) m = fmaxf(m, s[jj]);
#pragma unroll
        for (int d = 8; d >= 1; d >>= 1) m = fmaxf(m, __shfl_xor_sync(0xffffffffu, m, d));

        float sum = 0.f;
#pragma unroll
        for (int jj = 0; jj < 6; ++jj) { s[jj] = __expf(s[jj] - m); sum += s[jj]; }
#pragma unroll
        for (int d = 8; d >= 1; d >>= 1) sum += __shfl_xor_sync(0xffffffffu, sum, d);
        float inv = 1.0f / sum;

        const int rg = ty3 + i;
#pragma unroll
        for (int jj = 0; jj < 6; ++jj) {
            int jg = tx6 + jj;
            int off = jg - rg + 6;                 // ks-1-ks//2 = 6
            float bv = (off >= 0 && off < KS) ? kern[off] : 0.f;
            float val = fmaf(s[jj], inv, bv);
            if (TRANS) dst[jg * PCH + rg] = val;
            else       dst[rg * PCH + jg] = val;
        }
    }
}

extern "C" __global__ void __launch_bounds__(NT, 1)
dynconv_attn_kernel(const float* __restrict__ q, const float* __restrict__ k,
                    const float* __restrict__ v, const float* __restrict__ kh,
                    const float* __restrict__ kw, float* __restrict__ out) {
    extern __shared__ float smem[];
    float* b0  = smem;             // Q            -> A_w^T (after G2)
    float* b1  = b0 + BUFN;        // K            -> v1    (after G3)
    float* b2  = b1 + BUFN;        // V
    float* b3  = b2 + BUFN;        // K^T          -> A_h   (after G1)
    float* skh = b3 + BUFN;        // 13 floats
    float* skw = skh + 16;

    const int t   = threadIdx.x;
    const int tx6 = (t & 15) * 6;
    const int ty3 = (t >> 4) * 3;
    const int bc  = blockIdx.x;
    const int c   = bc & 255;                      // C = 256
    const size_t base = (size_t)bc * (HW * HW);

    // ---- Load Q,K,V (float4) + kernels ----
    {
        const float4* gq = reinterpret_cast<const float4*>(q + base);
        const float4* gk = reinterpret_cast<const float4*>(k + base);
        const float4* gv = reinterpret_cast<const float4*>(v + base);
#pragma unroll
        for (int it = 0; it < 4; ++it) {
            int i4  = t + NT * it;                 // 0..2047
            int row = i4 / 24;
            int col = (i4 - row * 24) * 4;
            *reinterpret_cast<float4*>(b0 + row * PCH + col) = gq[i4];
            *reinterpret_cast<float4*>(b1 + row * PCH + col) = gk[i4];
            *reinterpret_cast<float4*>(b2 + row * PCH + col) = gv[i4];
        }
        if (t < 256) {
            int i4  = 2048 + t;                    // 2048..2303
            int row = i4 / 24;
            int col = (i4 - row * 24) * 4;
            *reinterpret_cast<float4*>(b0 + row * PCH + col) = gq[i4];
            *reinterpret_cast<float4*>(b1 + row * PCH + col) = gk[i4];
            *reinterpret_cast<float4*>(b2 + row * PCH + col) = gv[i4];
        } else if (t < 256 + KS) {
            skh[t - 256] = kh[c * KS + (t - 256)];
        } else if (t < 256 + 2 * KS) {
            skw[t - 256 - KS] = kw[c * KS + (t - 256 - KS)];
        }
    }
    __syncthreads();

    // ---- Build K^T into b3 ----
#pragma unroll
    for (int it = 0; it < 18; ++it) {
        int idx = t + NT * it;                     // 0..9215
        int r   = idx / HW;
        int cc  = idx - r * HW;
        b3[cc * PCH + r] = b1[r * PCH + cc];
    }
    __syncthreads();

    u64 acc[3][3];

    // ---- G1: S_h[h][j] = sum_w Q[h][w] * K^T[w][j]  (A natural) ----
    gemm96<PCH, 1>(b0, b3, ty3, tx6, acc);
    __syncthreads();                               // all reads of b3 done
    // softmax rows h + band_h -> A_h natural into b3
    softmax_band_store<0>(acc, b3, skh, ty3, tx6);

    // ---- G2: S_w[w][j] = sum_h Q[h][w] * K[h][j]  (A k-major view of Q) ----
    gemm96<1, PCH>(b0, b1, ty3, tx6, acc);
    __syncthreads();                               // b0/b1 reads + b3 stores done
    // softmax rows w + band_w -> A_w^T into b0 (Q dead)
    softmax_band_store<1>(acc, b0, skw, ty3, tx6);

    // ---- G3: v1[h][w] = sum_j A_h[h][j] * V[j][w]  (A natural) ----
    gemm96<PCH, 1>(b3, b2, ty3, tx6, acc);
    // store v1 natural into b1 (K dead; b1 not read by G3)
#pragma unroll
    for (int i = 0; i < 3; ++i)
#pragma unroll
        for (int j2 = 0; j2 < 3; ++j2) {
            float2 f; unpack2(acc[i][j2], f.x, f.y);
            *reinterpret_cast<float2*>(b1 + (ty3 + i) * PCH + tx6 + 2 * j2) = f;
        }
    __syncthreads();                               // v1 + A_w^T visible

    // ---- G4: out[h][w] = sum_j v1[h][j] * A_w^T[j][w]  (A natural) ----
    gemm96<PCH, 1>(b1, b0, ty3, tx6, acc);
    {
        float* o = out + base;
#pragma unroll
        for (int i = 0; i < 3; ++i)
#pragma unroll
            for (int j2 = 0; j2 < 3; ++j2) {
                float2 f; unpack2(acc[i][j2], f.x, f.y);
                *reinterpret_cast<float2*>(o + (ty3 + i) * HW + tx6 + 2 * j2) = f;
            }
    }
}

extern "C" void kernel_launch(void* const* d_in, const int* in_sizes, int n_in,
                              void* d_out, int out_size) {
    const float* q  = (const float*)d_in[0];
    const float* k  = (const float*)d_in[1];
    const float* v  = (const float*)d_in[2];
    const float* kh = (const float*)d_in[3];
    const float* kw = (const float*)d_in[4];
    float* out = (float*)d_out;

    const int nbc = in_sizes[0] / (HW * HW);       // B*C = 2048
    const int smem_bytes = (4 * BUFN + 32) * (int)sizeof(float);  // 153728 B

    cudaFuncSetAttribute(dynconv_attn_kernel,
                         cudaFuncAttributeMaxDynamicSharedMemorySize, smem_bytes);

    dynconv_attn_kernel<<<nbc, NT, smem_bytes>>>(q, k, v, kh, kw, out);
}

// round 9
// speedup vs baseline: 1.1648x; 1.1648x over previous
#include <cuda_runtime.h>

// q,k,v: (8,256,96,96) f32; kernel_h/w: (256,13) f32; out f32 same shape.
// Per (b,c): 4 GEMMs 96^3 + 2 row-softmaxes + banded Toeplitz add.
// 256 threads/CTA, 6x6 register tile, f32x2 packed FMA, THREE smem buffers
// (110.3 KB) so 2 CTAs co-reside per SM -> 4 warps/SMSP.

#define HW    96
#define PCH   98             // even (8B LDS.64 align); 3 buffers fit 2 CTAs/SM
#define BUFN  (HW * PCH)     // 9408 floats
#define KS    13
#define NT    256

typedef unsigned long long u64;

__device__ __forceinline__ u64 splat2(float x) {
    u64 r; unsigned u = __float_as_uint(x);
    asm("mov.b64 %0, {%1, %2};" : "=l"(r) : "r"(u), "r"(u));
    return r;
}
__device__ __forceinline__ void unpack2(u64 v, float& x, float& y) {
    unsigned a, b;
    asm("mov.b64 {%0, %1}, %2;" : "=r"(a), "=r"(b) : "l"(v));
    x = __uint_as_float(a); y = __uint_as_float(b);
}
__device__ __forceinline__ void ffma2(u64& c, u64 a, u64 b) {
    asm("fma.rn.f32x2 %0, %1, %2, %0;" : "+l"(c) : "l"(a), "l"(b));
}
// float4 -> smem as two float2 (PCH=98 rows are only 8B-aligned)
__device__ __forceinline__ void st_f4(float* dst, float4 v) {
    *reinterpret_cast<float2*>(dst)     = make_float2(v.x, v.y);
    *reinterpret_cast<float2*>(dst + 2) = make_float2(v.z, v.w);
}

// C[m][n], 6x6 tile per thread (16x16 thread grid):
//   C[ty6+i][tx6+j] = sum_k A[(ty6+i)*AM + k*AK] * B[k*PCH + tx6+j]
// AM=PCH,AK=1: A natural [m][k].  AM=1,AK=PCH: A k-major [k][m].
template<int AM, int AK>
__device__ __forceinline__ void gemm96(const float* __restrict__ A,
                                       const float* __restrict__ B,
                                       int ty6, int tx6, u64 acc[6][3]) {
#pragma unroll
    for (int i = 0; i < 6; ++i)
#pragma unroll
        for (int j = 0; j < 3; ++j) acc[i][j] = 0ull;

    const float* ap = A + ty6 * AM;
    const float* bp = B + tx6;
#pragma unroll 2
    for (int kk = 0; kk < HW; ++kk) {
        u64 bv0 = *reinterpret_cast<const u64*>(bp);       // LDS.64, conflict-free
        u64 bv1 = *reinterpret_cast<const u64*>(bp + 2);
        u64 bv2 = *reinterpret_cast<const u64*>(bp + 4);
        u64 as[6];
#pragma unroll
        for (int i = 0; i < 6; ++i) as[i] = splat2(ap[i * AM]);
#pragma unroll
        for (int i = 0; i < 6; ++i) {
            ffma2(acc[i][0], as[i], bv0);
            ffma2(acc[i][1], as[i], bv1);
            ffma2(acc[i][2], as[i], bv2);
        }
        ap += AK; bp += PCH;
    }
}

// Row softmax (rows = m, across the 16 tx lanes) + Toeplitz band add.
// TRANS=0: dst[m][n]; TRANS=1: dst[n][m].
template<int TRANS>
__device__ __forceinline__ void softmax_band_store(u64 acc[6][3], float* __restrict__ dst,
                                                   const float* __restrict__ kern,
                                                   int ty6, int tx6) {
#pragma unroll
    for (int i = 0; i < 6; ++i) {
        float s[6];
        unpack2(acc[i][0], s[0], s[1]);
        unpack2(acc[i][1], s[2], s[3]);
        unpack2(acc[i][2], s[4], s[5]);

        float m = s[0];
#pragma unroll
        for (int jj = 1; jj < 6; ++jj) m = fmaxf(m, s[jj]);
#pragma unroll
        for (int d = 8; d >= 1; d >>= 1) m = fmaxf(m, __shfl_xor_sync(0xffffffffu, m, d));

        float sum = 0.f;
#pragma unroll
        for (int jj = 0; jj < 6; ++jj) { s[jj] = __expf(s[jj] - m); sum += s[jj]; }
#pragma unroll
        for (int d = 8; d >= 1; d >>= 1) sum += __shfl_xor_sync(0xffffffffu, sum, d);
        float inv = 1.0f / sum;

        const int rg = ty6 + i;
#pragma unroll
        for (int jj = 0; jj < 6; ++jj) {
            int jg = tx6 + jj;
            int off = jg - rg + 6;                 // ks-1-ks//2 = 6
            float bv = (off >= 0 && off < KS) ? kern[off] : 0.f;
            float val = fmaf(s[jj], inv, bv);
            if (TRANS) dst[jg * PCH + rg] = val;
            else       dst[rg * PCH + jg] = val;
        }
    }
}

extern "C" __global__ void __launch_bounds__(NT, 2)
dynconv_attn_kernel(const float* __restrict__ q, const float* __restrict__ k,
                    const float* __restrict__ v, const float* __restrict__ kh,
                    const float* __restrict__ kw, float* __restrict__ out) {
    extern __shared__ float smem[];
    float* b0  = smem;             // Q      -> A_w^T (after G2)
    float* b1  = b0 + BUFN;        // K      -> V     (after G2)
    float* b2  = b1 + BUFN;        // K^T    -> A_h   -> v1
    float* skh = b2 + BUFN;        // 13 floats
    float* skw = skh + 16;

    const int t   = threadIdx.x;
    const int tx6 = (t & 15) * 6;
    const int ty6 = (t >> 4) * 6;
    const int bc  = blockIdx.x;
    const int c   = bc & 255;                      // C = 256
    const size_t base = (size_t)bc * (HW * HW);

    // ---- Load Q,K (float4 from gmem) + per-channel kernels ----
    {
        const float4* gq = reinterpret_cast<const float4*>(q + base);
        const float4* gk = reinterpret_cast<const float4*>(k + base);
#pragma unroll
        for (int it = 0; it < 9; ++it) {
            int i4  = t + NT * it;                 // 0..2303
            int row = i4 / 24;
            int col = (i4 - row * 24) * 4;
            st_f4(b0 + row * PCH + col, gq[i4]);
            st_f4(b1 + row * PCH + col, gk[i4]);
        }
        if (t < KS)          skh[t]      = kh[c * KS + t];
        else if (t < 2 * KS) skw[t - KS] = kw[c * KS + (t - KS)];
    }
    __syncthreads();                               // (1)

    // ---- K^T into b2 ----
#pragma unroll
    for (int it = 0; it < 36; ++it) {
        int idx = t + NT * it;                     // 0..9215
        int r   = idx / HW;
        int cc  = idx - r * HW;
        b2[cc * PCH + r] = b1[r * PCH + cc];
    }
    __syncthreads();                               // (2)

    u64 acc[6][3];

    // ---- G1: S_h[h][j] = sum_w Q[h][w] * K^T[w][j] ----
    gemm96<PCH, 1>(b0, b2, ty6, tx6, acc);
    __syncthreads();                               // (3) all reads of b2 done
    // softmax rows h + band_h -> A_h natural into b2 (K^T dead)
    softmax_band_store<0>(acc, b2, skh, ty6, tx6);

    // ---- G2: S_w[w][j] = sum_h Q[h][w] * K[h][j]  (A = k-major view of Q) ----
    gemm96<1, PCH>(b0, b1, ty6, tx6, acc);
    __syncthreads();                               // (4) b0/b1 reads + A_h stores done
    // softmax rows w + band_w -> A_w^T into b0 (Q dead)
    softmax_band_store<1>(acc, b0, skw, ty6, tx6);
    // load V into b1 (K dead)
    {
        const float4* gv = reinterpret_cast<const float4*>(v + base);
#pragma unroll
        for (int it = 0; it < 9; ++it) {
            int i4  = t + NT * it;
            int row = i4 / 24;
            int col = (i4 - row * 24) * 4;
            st_f4(b1 + row * PCH + col, gv[i4]);
        }
    }
    __syncthreads();                               // (5)

    // ---- G3: v1[h][w] = sum_j A_h[h][j] * V[j][w] ----
    gemm96<PCH, 1>(b2, b1, ty6, tx6, acc);
    __syncthreads();                               // (6) all reads of b2 done
    // v1 natural into b2 (A_h dead)
#pragma unroll
    for (int i = 0; i < 6; ++i)
#pragma unroll
        for (int j2 = 0; j2 < 3; ++j2) {
            float2 f; unpack2(acc[i][j2], f.x, f.y);
            *reinterpret_cast<float2*>(b2 + (ty6 + i) * PCH + tx6 + 2 * j2) = f;
        }
    __syncthreads();                               // (7)

    // ---- G4: out[h][w] = sum_j v1[h][j] * A_w^T[j][w] ----
    gemm96<PCH, 1>(b2, b0, ty6, tx6, acc);
    {
        float* o = out + base;
#pragma unroll
        for (int i = 0; i < 6; ++i)
#pragma unroll
            for (int j2 = 0; j2 < 3; ++j2) {
                float2 f; unpack2(acc[i][j2], f.x, f.y);
                *reinterpret_cast<float2*>(o + (ty6 + i) * HW + tx6 + 2 * j2) = f;
            }
    }
}

extern "C" void kernel_launch(void* const* d_in, const int* in_sizes, int n_in,
                              void* d_out, int out_size) {
    const float* q  = (const float*)d_in[0];
    const float* k  = (const float*)d_in[1];
    const float* v  = (const float*)d_in[2];
    const float* kh = (const float*)d_in[3];
    const float* kw = (const float*)d_in[4];
    float* out = (float*)d_out;

    const int nbc = in_sizes[0] / (HW * HW);       // B*C = 2048
    const int smem_bytes = (3 * BUFN + 32) * (int)sizeof(float);  // 113,024 B

    cudaFuncSetAttribute(dynconv_attn_kernel,
                         cudaFuncAttributeMaxDynamicSharedMemorySize, smem_bytes);

    dynconv_attn_kernel<<<nbc, NT, smem_bytes>>>(q, k, v, kh, kw, out);
}

// round 10
// speedup vs baseline: 1.2507x; 1.0737x over previous
#include <cuda_runtime.h>

// q,k,v: (8,256,96,96) f32; kernel_h/w: (256,13) f32; out f32 same shape.
// Per (b,c): 4 GEMMs 96^3 + 2 row-softmaxes + banded Toeplitz add.
// 256 threads/CTA, 6x6 register tile, f32x2 packed FMA, THREE smem buffers
// (110.3 KB) so 2 CTAs/SM -> 4 warps/SMSP. k-loop software-pipelined:
// next iteration's smem loads issue before current iteration's FMAs.

#define HW    96
#define PCH   98             // even (8B LDS.64 align); 3 buffers fit 2 CTAs/SM
#define BUFN  (HW * PCH)     // 9408 floats
#define KS    13
#define NT    256

typedef unsigned long long u64;

__device__ __forceinline__ u64 splat2(float x) {
    u64 r; unsigned u = __float_as_uint(x);
    asm("mov.b64 %0, {%1, %2};" : "=l"(r) : "r"(u), "r"(u));
    return r;
}
__device__ __forceinline__ void unpack2(u64 v, float& x, float& y) {
    unsigned a, b;
    asm("mov.b64 {%0, %1}, %2;" : "=r"(a), "=r"(b) : "l"(v));
    x = __uint_as_float(a); y = __uint_as_float(b);
}
__device__ __forceinline__ void ffma2(u64& c, u64 a, u64 b) {
    asm("fma.rn.f32x2 %0, %1, %2, %0;" : "+l"(c) : "l"(a), "l"(b));
}
// float4 -> smem as two float2 (PCH=98 rows are only 8B-aligned)
__device__ __forceinline__ void st_f4(float* dst, float4 v) {
    *reinterpret_cast<float2*>(dst)     = make_float2(v.x, v.y);
    *reinterpret_cast<float2*>(dst + 2) = make_float2(v.z, v.w);
}

// C[m][n], 6x6 tile per thread (16x16 thread grid):
//   C[ty6+i][tx6+j] = sum_k A[(ty6+i)*AM + k*AK] * B[k*PCH + tx6+j]
// AM=PCH,AK=1: A natural [m][k].  AM=1,AK=PCH: A k-major [k][m].
// Software-pipelined: loads for k+1 issue before FMAs for k.
template<int AM, int AK>
__device__ __forceinline__ void gemm96(const float* __restrict__ A,
                                       const float* __restrict__ B,
                                       int ty6, int tx6, u64 acc[6][3]) {
#pragma unroll
    for (int i = 0; i < 6; ++i)
#pragma unroll
        for (int j = 0; j < 3; ++j) acc[i][j] = 0ull;

    const float* ap = A + ty6 * AM;
    const float* bp = B + tx6;

    // prologue: load k = 0
    u64 bv0 = *reinterpret_cast<const u64*>(bp);
    u64 bv1 = *reinterpret_cast<const u64*>(bp + 2);
    u64 bv2 = *reinterpret_cast<const u64*>(bp + 4);
    float av[6];
#pragma unroll
    for (int i = 0; i < 6; ++i) av[i] = ap[i * AM];

#pragma unroll 2
    for (int kk = 0; kk < HW - 1; ++kk) {
        bp += PCH; ap += AK;
        // prefetch k+1
        u64 nb0 = *reinterpret_cast<const u64*>(bp);
        u64 nb1 = *reinterpret_cast<const u64*>(bp + 2);
        u64 nb2 = *reinterpret_cast<const u64*>(bp + 4);
        float na[6];
#pragma unroll
        for (int i = 0; i < 6; ++i) na[i] = ap[i * AM];
        // FMAs for k
#pragma unroll
        for (int i = 0; i < 6; ++i) {
            u64 a = splat2(av[i]);
            ffma2(acc[i][0], a, bv0);
            ffma2(acc[i][1], a, bv1);
            ffma2(acc[i][2], a, bv2);
        }
        bv0 = nb0; bv1 = nb1; bv2 = nb2;
#pragma unroll
        for (int i = 0; i < 6; ++i) av[i] = na[i];
    }
    // epilogue: k = 95
#pragma unroll
    for (int i = 0; i < 6; ++i) {
        u64 a = splat2(av[i]);
        ffma2(acc[i][0], a, bv0);
        ffma2(acc[i][1], a, bv1);
        ffma2(acc[i][2], a, bv2);
    }
}

// Row softmax (rows = m, across the 16 tx lanes) + Toeplitz band add.
// TRANS=0: dst[m][n]; TRANS=1: dst[n][m].
template<int TRANS>
__device__ __forceinline__ void softmax_band_store(u64 acc[6][3], float* __restrict__ dst,
                                                   const float* __restrict__ kern,
                                                   int ty6, int tx6) {
#pragma unroll
    for (int i = 0; i < 6; ++i) {
        float s[6];
        unpack2(acc[i][0], s[0], s[1]);
        unpack2(acc[i][1], s[2], s[3]);
        unpack2(acc[i][2], s[4], s[5]);

        float m = s[0];
#pragma unroll
        for (int jj = 1; jj < 6; ++jj) m = fmaxf(m, s[jj]);
#pragma unroll
        for (int d = 8; d >= 1; d >>= 1) m = fmaxf(m, __shfl_xor_sync(0xffffffffu, m, d));

        float sum = 0.f;
#pragma unroll
        for (int jj = 0; jj < 6; ++jj) { s[jj] = __expf(s[jj] - m); sum += s[jj]; }
#pragma unroll
        for (int d = 8; d >= 1; d >>= 1) sum += __shfl_xor_sync(0xffffffffu, sum, d);
        float inv = 1.0f / sum;

        const int rg = ty6 + i;
#pragma unroll
        for (int jj = 0; jj < 6; ++jj) {
            int jg = tx6 + jj;
            int off = jg - rg + 6;                 // ks-1-ks//2 = 6
            float bv = (off >= 0 && off < KS) ? kern[off] : 0.f;
            float val = fmaf(s[jj], inv, bv);
            if (TRANS) dst[jg * PCH + rg] = val;
            else       dst[rg * PCH + jg] = val;
        }
    }
}

extern "C" __global__ void __launch_bounds__(NT, 2)
dynconv_attn_kernel(const float* __restrict__ q, const float* __restrict__ k,
                    const float* __restrict__ v, const float* __restrict__ kh,
                    const float* __restrict__ kw, float* __restrict__ out) {
    extern __shared__ float smem[];
    float* b0  = smem;             // Q      -> A_w^T (after G2)
    float* b1  = b0 + BUFN;        // K      -> V     (after G2)
    float* b2  = b1 + BUFN;        // K^T    -> A_h   -> v1
    float* skh = b2 + BUFN;        // 13 floats
    float* skw = skh + 16;

    const int t   = threadIdx.x;
    const int tx6 = (t & 15) * 6;
    const int ty6 = (t >> 4) * 6;
    const int bc  = blockIdx.x;
    const int c   = bc & 255;                      // C = 256
    const size_t base = (size_t)bc * (HW * HW);

    // ---- Load Q,K (float4 from gmem) + per-channel kernels ----
    {
        const float4* gq = reinterpret_cast<const float4*>(q + base);
        const float4* gk = reinterpret_cast<const float4*>(k + base);
#pragma unroll
        for (int it = 0; it < 9; ++it) {
            int i4  = t + NT * it;                 // 0..2303
            int row = i4 / 24;
            int col = (i4 - row * 24) * 4;
            st_f4(b0 + row * PCH + col, gq[i4]);
            st_f4(b1 + row * PCH + col, gk[i4]);
        }
        if (t < KS)          skh[t]      = kh[c * KS + t];
        else if (t < 2 * KS) skw[t - KS] = kw[c * KS + (t - KS)];
    }
    __syncthreads();                               // (1)

    // ---- K^T into b2 ----
#pragma unroll
    for (int it = 0; it < 36; ++it) {
        int idx = t + NT * it;                     // 0..9215
        int r   = idx / HW;
        int cc  = idx - r * HW;
        b2[cc * PCH + r] = b1[r * PCH + cc];
    }
    __syncthreads();                               // (2)

    u64 acc[6][3];

    // ---- G1: S_h[h][j] = sum_w Q[h][w] * K^T[w][j] ----
    gemm96<PCH, 1>(b0, b2, ty6, tx6, acc);
    __syncthreads();                               // (3) all reads of b2 done
    // softmax rows h + band_h -> A_h natural into b2 (K^T dead)
    softmax_band_store<0>(acc, b2, skh, ty6, tx6);

    // ---- G2: S_w[w][j] = sum_h Q[h][w] * K[h][j]  (A = k-major view of Q) ----
    gemm96<1, PCH>(b0, b1, ty6, tx6, acc);
    __syncthreads();                               // (4) b0/b1 reads + A_h stores done
    // softmax rows w + band_w -> A_w^T into b0 (Q dead)
    softmax_band_store<1>(acc, b0, skw, ty6, tx6);
    // load V into b1 (K dead)
    {
        const float4* gv = reinterpret_cast<const float4*>(v + base);
#pragma unroll
        for (int it = 0; it < 9; ++it) {
            int i4  = t + NT * it;
            int row = i4 / 24;
            int col = (i4 - row * 24) * 4;
            st_f4(b1 + row * PCH + col, gv[i4]);
        }
    }
    __syncthreads();                               // (5)

    // ---- G3: v1[h][w] = sum_j A_h[h][j] * V[j][w] ----
    gemm96<PCH, 1>(b2, b1, ty6, tx6, acc);
    __syncthreads();                               // (6) all reads of b2 done
    // v1 natural into b2 (A_h dead)
#pragma unroll
    for (int i = 0; i < 6; ++i)
#pragma unroll
        for (int j2 = 0; j2 < 3; ++j2) {
            float2 f; unpack2(acc[i][j2], f.x, f.y);
            *reinterpret_cast<float2*>(b2 + (ty6 + i) * PCH + tx6 + 2 * j2) = f;
        }
    __syncthreads();                               // (7)

    // ---- G4: out[h][w] = sum_j v1[h][j] * A_w^T[j][w] ----
    gemm96<PCH, 1>(b2, b0, ty6, tx6, acc);
    {
        float* o = out + base;
#pragma unroll
        for (int i = 0; i < 6; ++i)
#pragma unroll
            for (int j2 = 0; j2 < 3; ++j2) {
                float2 f; unpack2(acc[i][j2], f.x, f.y);
                *reinterpret_cast<float2*>(o + (ty6 + i) * HW + tx6 + 2 * j2) = f;
            }
    }
}

extern "C" void kernel_launch(void* const* d_in, const int* in_sizes, int n_in,
                              void* d_out, int out_size) {
    const float* q  = (const float*)d_in[0];
    const float* k  = (const float*)d_in[1];
    const float* v  = (const float*)d_in[2];
    const float* kh = (const float*)d_in[3];
    const float* kw = (const float*)d_in[4];
    float* out = (float*)d_out;

    const int nbc = in_sizes[0] / (HW * HW);       // B*C = 2048
    const int smem_bytes = (3 * BUFN + 32) * (int)sizeof(float);  // 113,024 B

    cudaFuncSetAttribute(dynconv_attn_kernel,
                         cudaFuncAttributeMaxDynamicSharedMemorySize, smem_bytes);

    dynconv_attn_kernel<<<nbc, NT, smem_bytes>>>(q, k, v, kh, kw, out);
}